// round 15
// baseline (speedup 1.0000x reference)
#include <cuda_runtime.h>
#include <math.h>

#define N_PTS 131072
#define M_NB  34
#define KKP   15
#define CIN   32
#define COUT  64
#define PPB   32      // points per block
#define TPB   128     // threads per block (4 warps)
#define WFS   484     // wf smem stride per point (16B aligned, bank-staggered)
#define WSTR  608     // per-warp w scratch stride (15*40 = 600 -> 608)

// scratch (static device globals are allowed; no runtime allocation)
__device__ float  g_raw[(size_t)N_PTS * COUT];
__device__ double g_sum[COUT];
__device__ double g_sq[COUT];

__global__ void zero_stats() {
    int t = threadIdx.x;
    if (t < COUT) { g_sum[t] = 0.0; g_sq[t] = 0.0; }
}

__global__ __launch_bounds__(TPB, 2) void kpconv_kernel(
    const float* __restrict__ xyz,
    const float* __restrict__ feats,
    const int*   __restrict__ nbr,
    const float* __restrict__ weight,
    const float* __restrict__ kpts)
{
    extern __shared__ float sm[];
    float* kp_s  = sm;                        // 48 floats (45 used)
    float* w_all = sm + 48;                   // 4 * 608
    float* wf_s  = sm + 2480;                 // 32 * 484
    float* wsm   = wf_s + PPB * WFS;          // 2048
    float* s_sum = wsm + 2048;                // 64
    float* s_sq  = s_sum + COUT;              // 64
    int*   j_all = (int*)(s_sq + COUT);       // 4 * 36

    const int tid  = threadIdx.x;
    const int lane = tid & 31;
    const int wid  = tid >> 5;
    const int base = blockIdx.x * PPB;

    if (tid < 45)   kp_s[tid] = kpts[tid];
    if (tid < COUT) { s_sum[tid] = 0.f; s_sq[tid] = 0.f; }
    __syncthreads();

    float* w_w = w_all + wid * WSTR;   // layout: w_w[k*40 + m]
    int*   j_w = j_all + wid * 36;

    // ---------------- Phase 1: per-point kernel weights + wf = w^T @ F ----------------
    // each warp handles 8 points; lane = input channel in the accumulation step
    for (int i = 0; i < 8; i++) {
        const int pl = wid * 8 + i;
        const int n  = base + pl;
        const float qx = xyz[3*n+0], qy = xyz[3*n+1], qz = xyz[3*n+2];

        // lanes cover neighbors m (lane, lane+32)
        for (int m = lane; m < M_NB; m += 32) {
            int j = nbr[n * M_NB + m];
            j_w[m] = j;
            float dx = xyz[3*j+0] - qx;
            float dy = xyz[3*j+1] - qy;
            float dz = xyz[3*j+2] - qz;
            #pragma unroll
            for (int k = 0; k < KKP; k++) {
                float ax = dx - kp_s[3*k+0];
                float ay = dy - kp_s[3*k+1];
                float az = dz - kp_s[3*k+2];
                float d2 = ax*ax + ay*ay + az*az;
                float w  = 1.0f - 25.0f * sqrtf(d2);   // 1/POINT_INFLUENCE = 25
                w_w[k*40 + m] = fmaxf(w, 0.0f);
            }
        }
        // pad m=34,35 with zero weight so the main loop runs in groups of 4
        if (lane < 2) {
            j_w[34 + lane] = 0;
            #pragma unroll
            for (int k = 0; k < KKP; k++) w_w[k*40 + 34 + lane] = 0.0f;
        }
        __syncwarp();

        float acc[KKP];
        #pragma unroll
        for (int k = 0; k < KKP; k++) acc[k] = 0.0f;

        #pragma unroll 3
        for (int g = 0; g < 9; g++) {
            int4 jv = *(const int4*)&j_w[g*4];
            float f0 = feats[jv.x * CIN + lane];   // one 128B line per warp
            float f1 = feats[jv.y * CIN + lane];
            float f2 = feats[jv.z * CIN + lane];
            float f3 = feats[jv.w * CIN + lane];
            #pragma unroll
            for (int k = 0; k < KKP; k++) {
                float4 w4 = *(const float4*)&w_w[k*40 + g*4];  // warp-broadcast
                acc[k] = fmaf(w4.x, f0, acc[k]);
                acc[k] = fmaf(w4.y, f1, acc[k]);
                acc[k] = fmaf(w4.z, f2, acc[k]);
                acc[k] = fmaf(w4.w, f3, acc[k]);
            }
        }
        #pragma unroll
        for (int k = 0; k < KKP; k++)
            wf_s[pl * WFS + k*32 + lane] = acc[k];
        __syncwarp();   // protect w_w / j_w reuse for next point
    }
    __syncthreads();

    // ---------------- Phase 2: out[32,64] = wf[32,480] @ W[480,64] ----------------
    // thread = (pg, dg): 4 points x 4 channels register tile
    const int dg = tid & 15;     // channel group: d = dg*4 .. dg*4+3
    const int pg = tid >> 4;     // point group : p = pg*4 .. pg*4+3
    float acc2[4][4];
    #pragma unroll
    for (int q = 0; q < 4; q++)
        #pragma unroll
        for (int j2 = 0; j2 < 4; j2++) acc2[q][j2] = 0.0f;

    for (int k = 0; k < KKP; k++) {
        __syncthreads();
        // stage weight[k] (32x64 floats) into smem
        const float4* wk = (const float4*)(weight + k * CIN * COUT);
        float4* wd = (float4*)wsm;
        #pragma unroll
        for (int t = 0; t < 4; t++) wd[tid + t*TPB] = wk[tid + t*TPB];
        __syncthreads();

        #pragma unroll
        for (int c4 = 0; c4 < 8; c4++) {
            float4 a0 = *(const float4*)&wf_s[(pg*4+0)*WFS + k*32 + c4*4];
            float4 a1 = *(const float4*)&wf_s[(pg*4+1)*WFS + k*32 + c4*4];
            float4 a2 = *(const float4*)&wf_s[(pg*4+2)*WFS + k*32 + c4*4];
            float4 a3 = *(const float4*)&wf_s[(pg*4+3)*WFS + k*32 + c4*4];
            #pragma unroll
            for (int cc = 0; cc < 4; cc++) {
                float4 b = *(const float4*)&wsm[(c4*4+cc)*COUT + dg*4];
                float a0c = (cc==0) ? a0.x : (cc==1) ? a0.y : (cc==2) ? a0.z : a0.w;
                float a1c = (cc==0) ? a1.x : (cc==1) ? a1.y : (cc==2) ? a1.z : a1.w;
                float a2c = (cc==0) ? a2.x : (cc==1) ? a2.y : (cc==2) ? a2.z : a2.w;
                float a3c = (cc==0) ? a3.x : (cc==1) ? a3.y : (cc==2) ? a3.z : a3.w;
                acc2[0][0] = fmaf(a0c, b.x, acc2[0][0]);
                acc2[0][1] = fmaf(a0c, b.y, acc2[0][1]);
                acc2[0][2] = fmaf(a0c, b.z, acc2[0][2]);
                acc2[0][3] = fmaf(a0c, b.w, acc2[0][3]);
                acc2[1][0] = fmaf(a1c, b.x, acc2[1][0]);
                acc2[1][1] = fmaf(a1c, b.y, acc2[1][1]);
                acc2[1][2] = fmaf(a1c, b.z, acc2[1][2]);
                acc2[1][3] = fmaf(a1c, b.w, acc2[1][3]);
                acc2[2][0] = fmaf(a2c, b.x, acc2[2][0]);
                acc2[2][1] = fmaf(a2c, b.y, acc2[2][1]);
                acc2[2][2] = fmaf(a2c, b.z, acc2[2][2]);
                acc2[2][3] = fmaf(a2c, b.w, acc2[2][3]);
                acc2[3][0] = fmaf(a3c, b.x, acc2[3][0]);
                acc2[3][1] = fmaf(a3c, b.y, acc2[3][1]);
                acc2[3][2] = fmaf(a3c, b.z, acc2[3][2]);
                acc2[3][3] = fmaf(a3c, b.w, acc2[3][3]);
            }
        }
    }

    // ---------------- Epilogue: store raw out + per-channel BN stats ----------------
    float csum[4] = {0,0,0,0}, csq[4] = {0,0,0,0};
    #pragma unroll
    for (int q = 0; q < 4; q++) {
        int n = base + pg*4 + q;
        float4 o = make_float4(acc2[q][0], acc2[q][1], acc2[q][2], acc2[q][3]);
        *(float4*)&g_raw[(size_t)n * COUT + dg*4] = o;
        #pragma unroll
        for (int j2 = 0; j2 < 4; j2++) {
            float v = acc2[q][j2];
            csum[j2] += v;
            csq[j2]  += v * v;
        }
    }
    #pragma unroll
    for (int j2 = 0; j2 < 4; j2++) {
        atomicAdd(&s_sum[dg*4 + j2], csum[j2]);
        atomicAdd(&s_sq [dg*4 + j2], csq[j2]);
    }
    __syncthreads();
    if (tid < COUT) {
        atomicAdd(&g_sum[tid], (double)s_sum[tid]);
        atomicAdd(&g_sq [tid], (double)s_sq [tid]);
    }
}

__global__ void bn_leaky(const float* __restrict__ gamma,
                         const float* __restrict__ beta,
                         float* __restrict__ out)
{
    __shared__ float sc[COUT], sh[COUT];
    int tid = threadIdx.x;
    if (tid < COUT) {
        float mean = (float)(g_sum[tid] * (1.0 / (double)N_PTS));
        float ex2  = (float)(g_sq [tid] * (1.0 / (double)N_PTS));
        float var  = ex2 - mean * mean;
        float s    = rsqrtf(var + 1e-5f) * gamma[tid];
        sc[tid] = s;
        sh[tid] = beta[tid] - mean * s;
    }
    __syncthreads();
    const float4* in4  = (const float4*)g_raw;
    float4*       out4 = (float4*)out;
    const int total = N_PTS * COUT / 4;
    for (int i = blockIdx.x * blockDim.x + tid; i < total; i += gridDim.x * blockDim.x) {
        float4 v = in4[i];
        int c = (i & 15) << 2;
        float r;
        r = fmaf(v.x, sc[c+0], sh[c+0]); v.x = (r >= 0.f) ? r : 0.2f * r;
        r = fmaf(v.y, sc[c+1], sh[c+1]); v.y = (r >= 0.f) ? r : 0.2f * r;
        r = fmaf(v.z, sc[c+2], sh[c+2]); v.z = (r >= 0.f) ? r : 0.2f * r;
        r = fmaf(v.w, sc[c+3], sh[c+3]); v.w = (r >= 0.f) ? r : 0.2f * r;
        out4[i] = v;
    }
}

extern "C" void kernel_launch(void* const* d_in, const int* in_sizes, int n_in,
                              void* d_out, int out_size)
{
    const float* xyz    = (const float*)d_in[0];
    const float* feats  = (const float*)d_in[1];
    const int*   nbr    = (const int*)  d_in[2];
    const float* weight = (const float*)d_in[3];
    const float* kpts   = (const float*)d_in[4];
    const float* gamma  = (const float*)d_in[5];
    const float* beta   = (const float*)d_in[6];
    float* out = (float*)d_out;

    // dynamic smem: (48 + 4*608 + 32*484 + 2048 + 64 + 64) floats + 4*36 ints = 81152 B
    const int smem_bytes = 81152;
    cudaFuncSetAttribute(kpconv_kernel,
                         cudaFuncAttributeMaxDynamicSharedMemorySize, smem_bytes);

    zero_stats<<<1, 64>>>();
    kpconv_kernel<<<N_PTS / PPB, TPB, smem_bytes>>>(xyz, feats, nbr, weight, kpts);
    bn_leaky<<<1024, 256>>>(gamma, beta, out);
}